// round 9
// baseline (speedup 1.0000x reference)
#include <cuda_runtime.h>
#include <cuda_fp16.h>
#include <cstdint>

#define NNODES 100000
#define EMAX   1600000
#define NGRAPH 64

// ---------------- device scratch ----------------
__device__ int    g_cnt[NNODES];
__device__ int    g_rowstart[NNODES];
__device__ int    g_cursor[NNODES];
__device__ int    g_blocksum[128];
__device__ int    g_csrsrc[EMAX];
__device__ float  g_dis[NNODES];
__device__ __half g_hs1h[NNODES * 32];    // fp16: x @ W1   (UNSCALED)
__device__ __half2 g_hs2h[NNODES * 32];   // fp16x2: dis * (lrelu(layer1) @ W2)
__device__ int    g_pool[NGRAPH * 64];

// ---------------- helpers ----------------
__device__ __forceinline__ int fenc(float v) {
    int i = __float_as_int(v);
    return i >= 0 ? i : (i ^ 0x7FFFFFFF);
}
__device__ __forceinline__ float fdec(int i) {
    return __int_as_float(i >= 0 ? i : (i ^ 0x7FFFFFFF));
}
__device__ __forceinline__ float lrelu(float v) { return v > 0.0f ? v : 0.1f * v; }

#define ENC_NEG_INF ((int)0x807FFFFF)
#define FNEG_INF    __int_as_float(0xFF800000)

// ---------------- kernels ----------------

// histogram of dst (int4-vectorized)
__global__ void k_count(const int* __restrict__ dst, int E) {
    int t = blockIdx.x * blockDim.x + threadIdx.x;
    int e4 = E >> 2;
    if (t < e4) {
        int4 d = reinterpret_cast<const int4*>(dst)[t];
        atomicAdd(&g_cnt[d.x], 1);
        atomicAdd(&g_cnt[d.y], 1);
        atomicAdd(&g_cnt[d.z], 1);
        atomicAdd(&g_cnt[d.w], 1);
    } else {
        int e = e4 * 4 + (t - e4);
        if (e < E) atomicAdd(&g_cnt[dst[e]], 1);
    }
}

// per-block (1024 elems) exclusive scan of g_cnt -> g_rowstart, block totals -> g_blocksum
// also writes g_dis (counts already in registers) and block 0 inits g_pool
__global__ void k_scan1(int Nn) {
    __shared__ int sT[256];
    int t = threadIdx.x;
    if (blockIdx.x == 0) {
        for (int i = t; i < NGRAPH * 64; i += 256) g_pool[i] = ENC_NEG_INF;
    }
    int base = blockIdx.x * 1024 + t * 4;
    int v0 = (base + 0 < Nn) ? g_cnt[base + 0] : 0;
    int v1 = (base + 1 < Nn) ? g_cnt[base + 1] : 0;
    int v2 = (base + 2 < Nn) ? g_cnt[base + 2] : 0;
    int v3 = (base + 3 < Nn) ? g_cnt[base + 3] : 0;
    if (base + 0 < Nn) g_dis[base + 0] = rsqrtf((float)v0 + 1.0f);
    if (base + 1 < Nn) g_dis[base + 1] = rsqrtf((float)v1 + 1.0f);
    if (base + 2 < Nn) g_dis[base + 2] = rsqrtf((float)v2 + 1.0f);
    if (base + 3 < Nn) g_dis[base + 3] = rsqrtf((float)v3 + 1.0f);
    int tot = v0 + v1 + v2 + v3;
    sT[t] = tot;
    __syncthreads();
    for (int off = 1; off < 256; off <<= 1) {
        int x = 0;
        if (t >= off) x = sT[t - off];
        __syncthreads();
        if (t >= off) sT[t] += x;
        __syncthreads();
    }
    int run = sT[t] - tot;
    if (base + 0 < Nn) g_rowstart[base + 0] = run; run += v0;
    if (base + 1 < Nn) g_rowstart[base + 1] = run; run += v1;
    if (base + 2 < Nn) g_rowstart[base + 2] = run; run += v2;
    if (base + 3 < Nn) g_rowstart[base + 3] = run;
    if (t == 255) g_blocksum[blockIdx.x] = sT[255];
}

// add block offsets (recompute 128-entry scan per block), init cursors
__global__ void k_scan3(int Nn, int NB) {
    __shared__ int s[128];
    int t = threadIdx.x;
    if (t < 128) s[t] = (t < NB) ? g_blocksum[t] : 0;
    __syncthreads();
    for (int off = 1; off < 128; off <<= 1) {
        int x = 0;
        if (t >= off && t < 128) x = s[t - off];
        __syncthreads();
        if (t >= off && t < 128) s[t] += x;
        __syncthreads();
    }
    int n = blockIdx.x * blockDim.x + t;
    if (n >= Nn) return;
    int bn = n >> 10;
    int off = (bn == 0) ? 0 : s[bn - 1];
    int rs = g_rowstart[n] + off;
    g_rowstart[n] = rs;
    g_cursor[n] = rs;
}

// scatter src ids into CSR (int4-vectorized)
__global__ void k_fill(const int* __restrict__ src, const int* __restrict__ dst, int E) {
    int t = blockIdx.x * blockDim.x + threadIdx.x;
    int e4 = E >> 2;
    if (t < e4) {
        int4 d = reinterpret_cast<const int4*>(dst)[t];
        int4 sc = reinterpret_cast<const int4*>(src)[t];
        g_csrsrc[atomicAdd(&g_cursor[d.x], 1)] = sc.x;
        g_csrsrc[atomicAdd(&g_cursor[d.y], 1)] = sc.y;
        g_csrsrc[atomicAdd(&g_cursor[d.z], 1)] = sc.z;
        g_csrsrc[atomicAdd(&g_cursor[d.w], 1)] = sc.w;
    } else {
        int e = e4 * 4 + (t - e4);
        if (e < E) g_csrsrc[atomicAdd(&g_cursor[dst[e]], 1)] = src[e];
    }
}

// hs1 = fp16( x @ W1 )  — UNSCALED: no dependencies, forked at t=0
__global__ void k_gemm1(const float* __restrict__ x, const float* __restrict__ W1, int Nn) {
    __shared__ float sW[128 * 32];
    for (int i = threadIdx.x; i < 128 * 32; i += blockDim.x) sW[i] = W1[i];
    __syncthreads();
    int warp = (blockIdx.x * blockDim.x + threadIdx.x) >> 5;
    int lane = threadIdx.x & 31;
    if (warp >= Nn) return;
    const float* xr = x + (size_t)warp * 128;
    float acc = 0.0f;
#pragma unroll
    for (int kt = 0; kt < 4; kt++) {
        float xk = xr[kt * 32 + lane];
#pragma unroll
        for (int kk = 0; kk < 32; kk++) {
            float xv = __shfl_sync(0xFFFFFFFFu, xk, kk);
            acc = fmaf(xv, sW[(kt * 32 + kk) * 32 + lane], acc);
        }
    }
    g_hs1h[(size_t)warp * 32 + lane] = __float2half_rn(acc);
}

// layer-1 aggregation (per-neighbor dis scaling) + lrelu + GEMM2, writes g_hs2h
__global__ void k_agg1(const float* __restrict__ b1, const float* __restrict__ W2, int Nn) {
    __shared__ float sW[32 * 64];
    for (int i = threadIdx.x; i < 32 * 64; i += blockDim.x) sW[i] = W2[i];
    __syncthreads();
    int warp = (blockIdx.x * blockDim.x + threadIdx.x) >> 5;
    int lane = threadIdx.x & 31;
    if (warp >= Nn) return;

    int rs = g_rowstart[warp];
    int cnt = g_cnt[warp];
    float a0 = 0.f, a1 = 0.f, a2 = 0.f, a3 = 0.f;
    for (int base = 0; base < cnt; base += 32) {
        int rem = cnt - base;
        int m = rem < 32 ? rem : 32;
        int sidx = 0;
        float dsl = 0.f;
        if (lane < m) {
            sidx = g_csrsrc[rs + base + lane];
            dsl = __ldg(&g_dis[sidx]);
        }
        int k = 0;
        for (; k + 4 <= m; k += 4) {
            int s0 = __shfl_sync(0xFFFFFFFFu, sidx, k);
            int s1 = __shfl_sync(0xFFFFFFFFu, sidx, k + 1);
            int s2 = __shfl_sync(0xFFFFFFFFu, sidx, k + 2);
            int s3 = __shfl_sync(0xFFFFFFFFu, sidx, k + 3);
            float d0 = __shfl_sync(0xFFFFFFFFu, dsl, k);
            float d1 = __shfl_sync(0xFFFFFFFFu, dsl, k + 1);
            float d2 = __shfl_sync(0xFFFFFFFFu, dsl, k + 2);
            float d3 = __shfl_sync(0xFFFFFFFFu, dsl, k + 3);
            a0 = fmaf(d0, __half2float(__ldg(&g_hs1h[(size_t)s0 * 32 + lane])), a0);
            a1 = fmaf(d1, __half2float(__ldg(&g_hs1h[(size_t)s1 * 32 + lane])), a1);
            a2 = fmaf(d2, __half2float(__ldg(&g_hs1h[(size_t)s2 * 32 + lane])), a2);
            a3 = fmaf(d3, __half2float(__ldg(&g_hs1h[(size_t)s3 * 32 + lane])), a3);
        }
        for (; k < m; k++) {
            int s = __shfl_sync(0xFFFFFFFFu, sidx, k);
            float dd = __shfl_sync(0xFFFFFFFFu, dsl, k);
            a0 = fmaf(dd, __half2float(__ldg(&g_hs1h[(size_t)s * 32 + lane])), a0);
        }
    }
    float d = g_dis[warp];
    float acc = (a0 + a1) + (a2 + a3);
    float self = __half2float(g_hs1h[(size_t)warp * 32 + lane]);  // unscaled h1
    float v = lrelu(d * (acc + d * self) + b1[lane]);

    // GEMM2 on registers: lane produces output feats (2*lane, 2*lane+1)
    const float2* sWp = reinterpret_cast<const float2*>(sW);
    float o0 = 0.f, o1 = 0.f;
#pragma unroll
    for (int kk = 0; kk < 32; kk++) {
        float xv = __shfl_sync(0xFFFFFFFFu, v, kk);
        float2 w = sWp[kk * 32 + lane];
        o0 = fmaf(xv, w.x, o0);
        o1 = fmaf(xv, w.y, o1);
    }
    g_hs2h[(size_t)warp * 32 + lane] = __floats2half2_rn(d * o0, d * o1);
}

// layer-2 aggregation + bias + fused global max pool (batch sorted)
__global__ void k_agg2(const float* __restrict__ b2, const int* __restrict__ batch, int Nn) {
    __shared__ float2 sv[8][32];
    __shared__ int sb[8];
    int wid = threadIdx.x >> 5;
    int lane = threadIdx.x & 31;
    int node = blockIdx.x * 8 + wid;
    bool valid = node < Nn;

    if (lane == 0) sb[wid] = valid ? batch[node] : -1;

    if (valid) {
        int rs = g_rowstart[node];
        int cnt = g_cnt[node];
        float ax0 = 0.f, ay0 = 0.f, ax1 = 0.f, ay1 = 0.f;
        float ax2 = 0.f, ay2 = 0.f, ax3 = 0.f, ay3 = 0.f;
        for (int base = 0; base < cnt; base += 32) {
            int rem = cnt - base;
            int m = rem < 32 ? rem : 32;
            int sidx = 0;
            if (lane < m) sidx = g_csrsrc[rs + base + lane];
            int k = 0;
            for (; k + 4 <= m; k += 4) {
                int s0 = __shfl_sync(0xFFFFFFFFu, sidx, k);
                int s1 = __shfl_sync(0xFFFFFFFFu, sidx, k + 1);
                int s2 = __shfl_sync(0xFFFFFFFFu, sidx, k + 2);
                int s3 = __shfl_sync(0xFFFFFFFFu, sidx, k + 3);
                float2 v0 = __half22float2(__ldg(&g_hs2h[(size_t)s0 * 32 + lane]));
                float2 v1 = __half22float2(__ldg(&g_hs2h[(size_t)s1 * 32 + lane]));
                float2 v2 = __half22float2(__ldg(&g_hs2h[(size_t)s2 * 32 + lane]));
                float2 v3 = __half22float2(__ldg(&g_hs2h[(size_t)s3 * 32 + lane]));
                ax0 += v0.x; ay0 += v0.y;
                ax1 += v1.x; ay1 += v1.y;
                ax2 += v2.x; ay2 += v2.y;
                ax3 += v3.x; ay3 += v3.y;
            }
            for (; k < m; k++) {
                int s = __shfl_sync(0xFFFFFFFFu, sidx, k);
                float2 v = __half22float2(__ldg(&g_hs2h[(size_t)s * 32 + lane]));
                ax0 += v.x; ay0 += v.y;
            }
        }
        float2 self = __half22float2(g_hs2h[(size_t)node * 32 + lane]);
        float2 bb = reinterpret_cast<const float2*>(b2)[lane];
        float d = g_dis[node];
        float2 o;
        o.x = d * ((ax0 + ax1) + (ax2 + ax3) + self.x) + bb.x;
        o.y = d * ((ay0 + ay1) + (ay2 + ay3) + self.y) + bb.y;
        sv[wid][lane] = o;
    }
    __syncthreads();

    if (threadIdx.x < 64) {
        int f = threadIdx.x;
        int half_ = f >> 1;
        int comp = f & 1;
        int curg = -1;
        float mx = FNEG_INF;
        for (int w = 0; w < 8; w++) {
            int bg = sb[w];
            if (bg < 0) continue;
            float2 p = sv[w][half_];
            float val = comp ? p.y : p.x;
            if (bg != curg) {
                if (curg >= 0) atomicMax(&g_pool[curg * 64 + f], fenc(mx));
                curg = bg;
                mx = FNEG_INF;
            }
            mx = fmaxf(mx, val);
        }
        if (curg >= 0) atomicMax(&g_pool[curg * 64 + f], fenc(mx));
    }
}

// MLP head, one block per graph: 64 -> 128 -> 64 -> 1
__global__ void k_mlp(const float* __restrict__ Wl1, const float* __restrict__ bl1,
                      const float* __restrict__ Wl2, const float* __restrict__ bl2,
                      const float* __restrict__ Wl3, const float* __restrict__ bl3,
                      float* __restrict__ out) {
    __shared__ float sg[64];
    __shared__ float st1[128];
    __shared__ float st2[64];
    int g = blockIdx.x;
    int t = threadIdx.x;

    if (t < 64) sg[t] = fdec(g_pool[g * 64 + t]);
    __syncthreads();
    {
        float s = bl1[t];
#pragma unroll 8
        for (int k = 0; k < 64; k++) s = fmaf(sg[k], Wl1[k * 128 + t], s);
        st1[t] = lrelu(s);
    }
    __syncthreads();
    if (t < 64) {
        float s = bl2[t];
#pragma unroll 8
        for (int k = 0; k < 128; k++) s = fmaf(st1[k], Wl2[k * 64 + t], s);
        st2[t] = lrelu(s);
    }
    __syncthreads();
    __shared__ float red[2];
    if (t < 64) {
        float p = st2[t] * Wl3[t];
#pragma unroll
        for (int off = 16; off > 0; off >>= 1)
            p += __shfl_down_sync(0xFFFFFFFFu, p, off);
        if ((t & 31) == 0) red[t >> 5] = p;
    }
    __syncthreads();
    if (t == 0) out[g] = red[0] + red[1] + bl3[0];
}

// ---------------- launch ----------------
extern "C" void kernel_launch(void* const* d_in, const int* in_sizes, int n_in,
                              void* d_out, int out_size) {
    const float* x   = (const float*)d_in[0];
    const int*   ei  = (const int*)d_in[1];
    const int*   bat = (const int*)d_in[2];
    const float* W1  = (const float*)d_in[3];
    const float* b1  = (const float*)d_in[4];
    const float* W2  = (const float*)d_in[5];
    const float* b2  = (const float*)d_in[6];
    const float* Wl1 = (const float*)d_in[7];
    const float* bl1 = (const float*)d_in[8];
    const float* Wl2 = (const float*)d_in[9];
    const float* bl2 = (const float*)d_in[10];
    const float* Wl3 = (const float*)d_in[11];
    const float* bl3 = (const float*)d_in[12];
    float* out = (float*)d_out;

    int Nn = in_sizes[0] / 128;
    int E  = in_sizes[1] / 2;
    const int* src = ei;
    const int* dst = ei + E;
    int NB = (Nn + 1023) / 1024;

    static cudaStream_t s2 = nullptr;
    static cudaEvent_t evFork = nullptr, evJoin = nullptr;
    static void* cntPtr = nullptr;
    if (s2 == nullptr) {
        cudaStreamCreateWithFlags(&s2, cudaStreamNonBlocking);
        cudaEventCreateWithFlags(&evFork, cudaEventDisableTiming);
        cudaEventCreateWithFlags(&evJoin, cudaEventDisableTiming);
        cudaGetSymbolAddress(&cntPtr, g_cnt);
    }

    // fork at t=0: gemm1 (unscaled) depends on nothing but x, W1
    cudaEventRecord(evFork, 0);
    cudaStreamWaitEvent(s2, evFork, 0);
    k_gemm1<<<(Nn + 7) / 8, 256, 0, s2>>>(x, W1, Nn);
    cudaEventRecord(evJoin, s2);

    // main stream: CSR build (+dis +pool init inside scan1)
    cudaMemsetAsync(cntPtr, 0, NNODES * sizeof(int), 0);
    {
        int nThreads = (E >> 2) + (E & 3);
        k_count<<<(nThreads + 255) / 256, 256>>>(dst, E);
    }
    k_scan1<<<NB, 256>>>(Nn);
    k_scan3<<<(Nn + 255) / 256, 256>>>(Nn, NB);
    {
        int nThreads = (E >> 2) + (E & 3);
        k_fill<<<(nThreads + 255) / 256, 256>>>(src, dst, E);
    }

    // join, then the serial tail
    cudaStreamWaitEvent(0, evJoin, 0);
    k_agg1<<<(Nn + 7) / 8, 256>>>(b1, W2, Nn);
    k_agg2<<<(Nn + 7) / 8, 256>>>(b2, bat, Nn);
    k_mlp<<<NGRAPH, 128>>>(Wl1, bl1, Wl2, bl2, Wl3, bl3, out);
}

// round 10
// speedup vs baseline: 1.0464x; 1.0464x over previous
#include <cuda_runtime.h>
#include <cuda_fp16.h>
#include <cstdint>

#define NNODES 100000
#define EMAX   1600000
#define NGRAPH 64

// ---------------- device scratch ----------------
__device__ int    g_cnt[NNODES];
__device__ int    g_rowstart[NNODES];
__device__ int    g_cursor[NNODES];
__device__ int    g_blocksum[128];
__device__ int    g_csrsrc[EMAX];
__device__ float  g_dis[NNODES];
__device__ __half g_hs1h[NNODES * 32];    // fp16: dis * (x @ W1)
__device__ __half2 g_hs2h[NNODES * 32];   // fp16x2: dis * (lrelu(layer1) @ W2)
__device__ int    g_pool[NGRAPH * 64];

// ---------------- helpers ----------------
__device__ __forceinline__ int fenc(float v) {
    int i = __float_as_int(v);
    return i >= 0 ? i : (i ^ 0x7FFFFFFF);
}
__device__ __forceinline__ float fdec(int i) {
    return __int_as_float(i >= 0 ? i : (i ^ 0x7FFFFFFF));
}
__device__ __forceinline__ float lrelu(float v) { return v > 0.0f ? v : 0.1f * v; }

#define ENC_NEG_INF ((int)0x807FFFFF)
#define FNEG_INF    __int_as_float(0xFF800000)

// ---------------- kernels ----------------

__global__ void k_nop() {}

// histogram of dst (int4-vectorized)
__global__ void k_count(const int* __restrict__ dst, int E) {
    int t = blockIdx.x * blockDim.x + threadIdx.x;
    int e4 = E >> 2;
    if (t < e4) {
        int4 d = reinterpret_cast<const int4*>(dst)[t];
        atomicAdd(&g_cnt[d.x], 1);
        atomicAdd(&g_cnt[d.y], 1);
        atomicAdd(&g_cnt[d.z], 1);
        atomicAdd(&g_cnt[d.w], 1);
    } else {
        int e = e4 * 4 + (t - e4);
        if (e < E) atomicAdd(&g_cnt[dst[e]], 1);
    }
}

// per-block (1024 elems) exclusive scan of g_cnt -> g_rowstart, block totals -> g_blocksum
// also writes g_dis and block 0 inits g_pool
__global__ void k_scan1(int Nn) {
    __shared__ int sT[256];
    int t = threadIdx.x;
    if (blockIdx.x == 0) {
        for (int i = t; i < NGRAPH * 64; i += 256) g_pool[i] = ENC_NEG_INF;
    }
    int base = blockIdx.x * 1024 + t * 4;
    int v0 = (base + 0 < Nn) ? g_cnt[base + 0] : 0;
    int v1 = (base + 1 < Nn) ? g_cnt[base + 1] : 0;
    int v2 = (base + 2 < Nn) ? g_cnt[base + 2] : 0;
    int v3 = (base + 3 < Nn) ? g_cnt[base + 3] : 0;
    if (base + 0 < Nn) g_dis[base + 0] = rsqrtf((float)v0 + 1.0f);
    if (base + 1 < Nn) g_dis[base + 1] = rsqrtf((float)v1 + 1.0f);
    if (base + 2 < Nn) g_dis[base + 2] = rsqrtf((float)v2 + 1.0f);
    if (base + 3 < Nn) g_dis[base + 3] = rsqrtf((float)v3 + 1.0f);
    int tot = v0 + v1 + v2 + v3;
    sT[t] = tot;
    __syncthreads();
    for (int off = 1; off < 256; off <<= 1) {
        int x = 0;
        if (t >= off) x = sT[t - off];
        __syncthreads();
        if (t >= off) sT[t] += x;
        __syncthreads();
    }
    int run = sT[t] - tot;
    if (base + 0 < Nn) g_rowstart[base + 0] = run; run += v0;
    if (base + 1 < Nn) g_rowstart[base + 1] = run; run += v1;
    if (base + 2 < Nn) g_rowstart[base + 2] = run; run += v2;
    if (base + 3 < Nn) g_rowstart[base + 3] = run;
    if (t == 255) g_blocksum[blockIdx.x] = sT[255];
}

// add block offsets (recompute 128-entry scan per block), init cursors
__global__ void k_scan3(int Nn, int NB) {
    __shared__ int s[128];
    int t = threadIdx.x;
    if (t < 128) s[t] = (t < NB) ? g_blocksum[t] : 0;
    __syncthreads();
    for (int off = 1; off < 128; off <<= 1) {
        int x = 0;
        if (t >= off && t < 128) x = s[t - off];
        __syncthreads();
        if (t >= off && t < 128) s[t] += x;
        __syncthreads();
    }
    int n = blockIdx.x * blockDim.x + t;
    if (n >= Nn) return;
    int bn = n >> 10;
    int off = (bn == 0) ? 0 : s[bn - 1];
    int rs = g_rowstart[n] + off;
    g_rowstart[n] = rs;
    g_cursor[n] = rs;
}

// scatter src ids into CSR (int4-vectorized)
__global__ void k_fill(const int* __restrict__ src, const int* __restrict__ dst, int E) {
    int t = blockIdx.x * blockDim.x + threadIdx.x;
    int e4 = E >> 2;
    if (t < e4) {
        int4 d = reinterpret_cast<const int4*>(dst)[t];
        int4 sc = reinterpret_cast<const int4*>(src)[t];
        g_csrsrc[atomicAdd(&g_cursor[d.x], 1)] = sc.x;
        g_csrsrc[atomicAdd(&g_cursor[d.y], 1)] = sc.y;
        g_csrsrc[atomicAdd(&g_cursor[d.z], 1)] = sc.z;
        g_csrsrc[atomicAdd(&g_cursor[d.w], 1)] = sc.w;
    } else {
        int e = e4 * 4 + (t - e4);
        if (e < E) g_csrsrc[atomicAdd(&g_cursor[dst[e]], 1)] = src[e];
    }
}

// hs1 = fp16( dis * (x @ W1) )
__global__ void k_gemm1(const float* __restrict__ x, const float* __restrict__ W1, int Nn) {
    __shared__ float sW[128 * 32];
    for (int i = threadIdx.x; i < 128 * 32; i += blockDim.x) sW[i] = W1[i];
    __syncthreads();
    int warp = (blockIdx.x * blockDim.x + threadIdx.x) >> 5;
    int lane = threadIdx.x & 31;
    if (warp >= Nn) return;
    const float* xr = x + (size_t)warp * 128;
    float acc = 0.0f;
#pragma unroll
    for (int kt = 0; kt < 4; kt++) {
        float xk = xr[kt * 32 + lane];
#pragma unroll
        for (int kk = 0; kk < 32; kk++) {
            float xv = __shfl_sync(0xFFFFFFFFu, xk, kk);
            acc = fmaf(xv, sW[(kt * 32 + kk) * 32 + lane], acc);
        }
    }
    g_hs1h[(size_t)warp * 32 + lane] = __float2half_rn(g_dis[warp] * acc);
}

// layer-1 aggregation + lrelu + GEMM2, writes g_hs2h (half2)
__global__ void k_agg1(const float* __restrict__ b1, const float* __restrict__ W2, int Nn) {
    __shared__ float sW[32 * 64];
    for (int i = threadIdx.x; i < 32 * 64; i += blockDim.x) sW[i] = W2[i];
    __syncthreads();
    int warp = (blockIdx.x * blockDim.x + threadIdx.x) >> 5;
    int lane = threadIdx.x & 31;
    if (warp >= Nn) return;

    int rs = g_rowstart[warp];
    int cnt = g_cnt[warp];
    float a0 = 0.f, a1 = 0.f, a2 = 0.f, a3 = 0.f;
    for (int base = 0; base < cnt; base += 32) {
        int rem = cnt - base;
        int m = rem < 32 ? rem : 32;
        int sidx = 0;
        if (lane < m) sidx = g_csrsrc[rs + base + lane];
        int k = 0;
        for (; k + 4 <= m; k += 4) {
            int s0 = __shfl_sync(0xFFFFFFFFu, sidx, k);
            int s1 = __shfl_sync(0xFFFFFFFFu, sidx, k + 1);
            int s2 = __shfl_sync(0xFFFFFFFFu, sidx, k + 2);
            int s3 = __shfl_sync(0xFFFFFFFFu, sidx, k + 3);
            a0 += __half2float(__ldg(&g_hs1h[(size_t)s0 * 32 + lane]));
            a1 += __half2float(__ldg(&g_hs1h[(size_t)s1 * 32 + lane]));
            a2 += __half2float(__ldg(&g_hs1h[(size_t)s2 * 32 + lane]));
            a3 += __half2float(__ldg(&g_hs1h[(size_t)s3 * 32 + lane]));
        }
        for (; k < m; k++) {
            int s = __shfl_sync(0xFFFFFFFFu, sidx, k);
            a0 += __half2float(__ldg(&g_hs1h[(size_t)s * 32 + lane]));
        }
    }
    float d = g_dis[warp];
    float acc = (a0 + a1) + (a2 + a3);
    float self = __half2float(g_hs1h[(size_t)warp * 32 + lane]);
    float v = lrelu(d * (acc + self) + b1[lane]);

    const float2* sWp = reinterpret_cast<const float2*>(sW);
    float o0 = 0.f, o1 = 0.f;
#pragma unroll
    for (int kk = 0; kk < 32; kk++) {
        float xv = __shfl_sync(0xFFFFFFFFu, v, kk);
        float2 w = sWp[kk * 32 + lane];
        o0 = fmaf(xv, w.x, o0);
        o1 = fmaf(xv, w.y, o1);
    }
    g_hs2h[(size_t)warp * 32 + lane] = __floats2half2_rn(d * o0, d * o1);
}

// layer-2 aggregation + bias + fused global max pool (batch sorted)
__global__ void k_agg2(const float* __restrict__ b2, const int* __restrict__ batch, int Nn) {
    __shared__ float2 sv[8][32];
    __shared__ int sb[8];
    int wid = threadIdx.x >> 5;
    int lane = threadIdx.x & 31;
    int node = blockIdx.x * 8 + wid;
    bool valid = node < Nn;

    if (lane == 0) sb[wid] = valid ? batch[node] : -1;

    if (valid) {
        int rs = g_rowstart[node];
        int cnt = g_cnt[node];
        float ax0 = 0.f, ay0 = 0.f, ax1 = 0.f, ay1 = 0.f;
        float ax2 = 0.f, ay2 = 0.f, ax3 = 0.f, ay3 = 0.f;
        for (int base = 0; base < cnt; base += 32) {
            int rem = cnt - base;
            int m = rem < 32 ? rem : 32;
            int sidx = 0;
            if (lane < m) sidx = g_csrsrc[rs + base + lane];
            int k = 0;
            for (; k + 4 <= m; k += 4) {
                int s0 = __shfl_sync(0xFFFFFFFFu, sidx, k);
                int s1 = __shfl_sync(0xFFFFFFFFu, sidx, k + 1);
                int s2 = __shfl_sync(0xFFFFFFFFu, sidx, k + 2);
                int s3 = __shfl_sync(0xFFFFFFFFu, sidx, k + 3);
                float2 v0 = __half22float2(__ldg(&g_hs2h[(size_t)s0 * 32 + lane]));
                float2 v1 = __half22float2(__ldg(&g_hs2h[(size_t)s1 * 32 + lane]));
                float2 v2 = __half22float2(__ldg(&g_hs2h[(size_t)s2 * 32 + lane]));
                float2 v3 = __half22float2(__ldg(&g_hs2h[(size_t)s3 * 32 + lane]));
                ax0 += v0.x; ay0 += v0.y;
                ax1 += v1.x; ay1 += v1.y;
                ax2 += v2.x; ay2 += v2.y;
                ax3 += v3.x; ay3 += v3.y;
            }
            for (; k < m; k++) {
                int s = __shfl_sync(0xFFFFFFFFu, sidx, k);
                float2 v = __half22float2(__ldg(&g_hs2h[(size_t)s * 32 + lane]));
                ax0 += v.x; ay0 += v.y;
            }
        }
        float2 self = __half22float2(g_hs2h[(size_t)node * 32 + lane]);
        float2 bb = reinterpret_cast<const float2*>(b2)[lane];
        float d = g_dis[node];
        float2 o;
        o.x = d * ((ax0 + ax1) + (ax2 + ax3) + self.x) + bb.x;
        o.y = d * ((ay0 + ay1) + (ay2 + ay3) + self.y) + bb.y;
        sv[wid][lane] = o;
    }
    __syncthreads();

    if (threadIdx.x < 64) {
        int f = threadIdx.x;
        int half_ = f >> 1;
        int comp = f & 1;
        int curg = -1;
        float mx = FNEG_INF;
        for (int w = 0; w < 8; w++) {
            int bg = sb[w];
            if (bg < 0) continue;
            float2 p = sv[w][half_];
            float val = comp ? p.y : p.x;
            if (bg != curg) {
                if (curg >= 0) atomicMax(&g_pool[curg * 64 + f], fenc(mx));
                curg = bg;
                mx = FNEG_INF;
            }
            mx = fmaxf(mx, val);
        }
        if (curg >= 0) atomicMax(&g_pool[curg * 64 + f], fenc(mx));
    }
}

// MLP head, one block per graph: 64 -> 128 -> 64 -> 1
__global__ void k_mlp(const float* __restrict__ Wl1, const float* __restrict__ bl1,
                      const float* __restrict__ Wl2, const float* __restrict__ bl2,
                      const float* __restrict__ Wl3, const float* __restrict__ bl3,
                      float* __restrict__ out) {
    __shared__ float sg[64];
    __shared__ float st1[128];
    __shared__ float st2[64];
    int g = blockIdx.x;
    int t = threadIdx.x;

    if (t < 64) sg[t] = fdec(g_pool[g * 64 + t]);
    __syncthreads();
    {
        float s = bl1[t];
#pragma unroll 8
        for (int k = 0; k < 64; k++) s = fmaf(sg[k], Wl1[k * 128 + t], s);
        st1[t] = lrelu(s);
    }
    __syncthreads();
    if (t < 64) {
        float s = bl2[t];
#pragma unroll 8
        for (int k = 0; k < 128; k++) s = fmaf(st1[k], Wl2[k * 64 + t], s);
        st2[t] = lrelu(s);
    }
    __syncthreads();
    __shared__ float red[2];
    if (t < 64) {
        float p = st2[t] * Wl3[t];
#pragma unroll
        for (int off = 16; off > 0; off >>= 1)
            p += __shfl_down_sync(0xFFFFFFFFu, p, off);
        if ((t & 31) == 0) red[t >> 5] = p;
    }
    __syncthreads();
    if (t == 0) out[g] = red[0] + red[1] + bl3[0];
}

// ---------------- launch ----------------
// Stream roles swapped vs R8: CSR build on s2, compute chain on main stream.
// Main-stream launch order: gemm1(0), nop(1), agg1(2), agg2(3) <- ncu capture, mlp(4)
extern "C" void kernel_launch(void* const* d_in, const int* in_sizes, int n_in,
                              void* d_out, int out_size) {
    const float* x   = (const float*)d_in[0];
    const int*   ei  = (const int*)d_in[1];
    const int*   bat = (const int*)d_in[2];
    const float* W1  = (const float*)d_in[3];
    const float* b1  = (const float*)d_in[4];
    const float* W2  = (const float*)d_in[5];
    const float* b2  = (const float*)d_in[6];
    const float* Wl1 = (const float*)d_in[7];
    const float* bl1 = (const float*)d_in[8];
    const float* Wl2 = (const float*)d_in[9];
    const float* bl2 = (const float*)d_in[10];
    const float* Wl3 = (const float*)d_in[11];
    const float* bl3 = (const float*)d_in[12];
    float* out = (float*)d_out;

    int Nn = in_sizes[0] / 128;
    int E  = in_sizes[1] / 2;
    const int* src = ei;
    const int* dst = ei + E;
    int NB = (Nn + 1023) / 1024;

    static cudaStream_t s2 = nullptr;
    static cudaEvent_t evFork = nullptr, evDis = nullptr, evCSR = nullptr;
    static void* cntPtr = nullptr;
    if (s2 == nullptr) {
        cudaStreamCreateWithFlags(&s2, cudaStreamNonBlocking);
        cudaEventCreateWithFlags(&evFork, cudaEventDisableTiming);
        cudaEventCreateWithFlags(&evDis, cudaEventDisableTiming);
        cudaEventCreateWithFlags(&evCSR, cudaEventDisableTiming);
        cudaGetSymbolAddress(&cntPtr, g_cnt);
    }

    // fork s2 off the captured (main) stream
    cudaEventRecord(evFork, 0);
    cudaStreamWaitEvent(s2, evFork, 0);

    // s2: CSR build chain
    cudaMemsetAsync(cntPtr, 0, NNODES * sizeof(int), s2);
    {
        int nThreads = (E >> 2) + (E & 3);
        k_count<<<(nThreads + 255) / 256, 256, 0, s2>>>(dst, E);
    }
    k_scan1<<<NB, 256, 0, s2>>>(Nn);          // g_dis + pool init ready here
    cudaEventRecord(evDis, s2);
    k_scan3<<<(Nn + 255) / 256, 256, 0, s2>>>(Nn, NB);
    {
        int nThreads = (E >> 2) + (E & 3);
        k_fill<<<(nThreads + 255) / 256, 256, 0, s2>>>(src, dst, E);
    }
    cudaEventRecord(evCSR, s2);

    // main: gemm1 (waits for dis), overlaps scan3+fill on s2
    cudaStreamWaitEvent(0, evDis, 0);
    k_gemm1<<<(Nn + 7) / 8, 256>>>(x, W1, Nn);       // main idx 0
    k_nop<<<1, 32>>>();                               // main idx 1

    // main: aggregation tail (waits for CSR)
    cudaStreamWaitEvent(0, evCSR, 0);
    k_agg1<<<(Nn + 7) / 8, 256>>>(b1, W2, Nn);       // main idx 2
    k_agg2<<<(Nn + 7) / 8, 256>>>(b2, bat, Nn);      // main idx 3  <- ncu capture
    k_mlp<<<NGRAPH, 128>>>(Wl1, bl1, Wl2, bl2, Wl3, bl3, out);  // main idx 4
}